// round 16
// baseline (speedup 1.0000x reference)
#include <cuda_runtime.h>
#include <cuda_bf16.h>

#define Nn 50000
#define Ee 800000
#define Dd 256
#define Fin 64
#define Bg 1000
#define BN_EPS 1e-5f

typedef unsigned long long ull;

// ---------------- scratch (device globals; no allocation) ----------------
__device__ float g_mm[Nn * Dd];      // matmul output
__device__ float g_agg[Nn * Dd];     // aggregated
__device__ float g_h[Nn * Dd];       // layer activation
__device__ float g_ax[Nn * Fin];     // S @ x  (layer-0 pre-aggregated input)
__device__ int   g_cnt[Nn];
__device__ float g_dinv[Nn];
__device__ int   g_off[Nn + 1];
__device__ int   g_cur[Nn];
__device__ int   g_ssrc[Ee];
__device__ float g_coef[Ee];
__device__ float g_sum[Dd];
__device__ float g_sumsq[Dd];

// ---------------- f32x2 helper ----------------
__device__ __forceinline__ void ffma2(ull& d, ull a, ull b) {
    asm("fma.rn.f32x2 %0, %1, %2, %0;" : "+l"(d) : "l"(a), "l"(b));
}
__device__ __forceinline__ float tanh_fast(float x) {
    float y;
    asm("tanh.approx.f32 %0, %1;" : "=f"(y) : "f"(x));
    return y;
}

// ---------------- graph preprocessing ----------------
__global__ void k_zero_graph() {
    int i = blockIdx.x * blockDim.x + threadIdx.x;
    if (i < Nn) { g_cnt[i] = 0; g_cur[i] = 0; }
}

__global__ void k_degree(const int* __restrict__ ei) {
    int e = blockIdx.x * blockDim.x + threadIdx.x;
    if (e < Ee) atomicAdd(&g_cnt[ei[Ee + e]], 1);
}

__global__ void k_scan() {
    const int T = 1024;
    const int chunk = (Nn + T - 1) / T;
    __shared__ int s[T];
    int t = threadIdx.x;
    int beg = t * chunk;
    int end = beg + chunk; if (end > Nn) end = Nn;
    int loc = 0;
    for (int i = beg; i < end; i++) loc += g_cnt[i];
    s[t] = loc;
    __syncthreads();
    for (int d = 1; d < T; d <<= 1) {
        int v = (t >= d) ? s[t - d] : 0;
        __syncthreads();
        s[t] += v;
        __syncthreads();
    }
    int prefix = (t == 0) ? 0 : s[t - 1];
    for (int i = beg; i < end; i++) {
        g_off[i] = prefix;
        prefix += g_cnt[i];
    }
    if (t == T - 1) g_off[Nn] = prefix;
    for (int i = t; i < Nn; i += T) g_dinv[i] = rsqrtf(1.0f + (float)g_cnt[i]);
}

__global__ void k_scatter(const int* __restrict__ ei) {
    int e = blockIdx.x * blockDim.x + threadIdx.x;
    if (e >= Ee) return;
    int s = ei[e];
    int d = ei[Ee + e];
    int pos = g_off[d] + atomicAdd(&g_cur[d], 1);
    g_ssrc[pos] = s;
    g_coef[pos] = g_dinv[s] * g_dinv[d];
}

// ---------------- SGEMM (pure FFMA2): C[N,Dd] = A[N,K] @ W[K,Dd] ----------
// BM=128, BN=128, BK=16, 256 threads, 8x8 micro-tile = 8x4 f32x2 pairs.
// A tile stored DUPLICATED in smem: As2[k][2m]=As2[k][2m+1]=A[m], so one
// LDS.128 delivers two packed (a,a) u64 operands — no MOV packing at all.
// sel: 0 -> A = g_h (K=256), 1 -> A = g_ax (K=64)
__global__ __launch_bounds__(256, 2)
void k_gemm(const float* __restrict__ W, int K, int sel) {
    const int BK = 16;
    __shared__ __align__(16) float As2[BK][256];   // 16 KB (duplicated)
    __shared__ __align__(16) float Bs[BK][128];    // 8 KB

    int bn = blockIdx.x;
    int bm = blockIdx.y;
    int tid = threadIdx.x;
    int tx = tid & 15, ty = tid >> 4;
    int rowBase = bm * 128;

    const float* Abase = sel ? g_ax : g_h;

    ull acc[8][4];
#pragma unroll
    for (int i = 0; i < 8; i++)
#pragma unroll
        for (int j = 0; j < 4; j++) acc[i][j] = 0ull;

    for (int k0 = 0; k0 < K; k0 += BK) {
        // A tile: 128 rows x 16 k, duplicated along m
#pragma unroll
        for (int l = 0; l < 2; l++) {
            int idx = tid * 2 + l;        // 0..511
            int m = idx >> 2;             // 0..127
            int k4 = idx & 3;             // 0..3
            int grow = rowBase + m;
            float4 v = make_float4(0.f, 0.f, 0.f, 0.f);
            if (grow < Nn)
                v = *(const float4*)&Abase[(size_t)grow * K + k0 + k4 * 4];
            int mm = 2 * m;
            As2[k4 * 4 + 0][mm] = v.x; As2[k4 * 4 + 0][mm + 1] = v.x;
            As2[k4 * 4 + 1][mm] = v.y; As2[k4 * 4 + 1][mm + 1] = v.y;
            As2[k4 * 4 + 2][mm] = v.z; As2[k4 * 4 + 2][mm + 1] = v.z;
            As2[k4 * 4 + 3][mm] = v.w; As2[k4 * 4 + 3][mm + 1] = v.w;
        }
        // B tile: 16 x 128
#pragma unroll
        for (int l = 0; l < 2; l++) {
            int idx = tid * 2 + l;
            int k = idx >> 5;
            int n4 = idx & 31;
            float4 v = *(const float4*)&W[(size_t)(k0 + k) * Dd + bn * 128 + n4 * 4];
            *(float4*)&Bs[k][n4 * 4] = v;
        }
        __syncthreads();
#pragma unroll
        for (int k = 0; k < BK; k++) {
            ulonglong2 a01 = *(const ulonglong2*)&As2[k][ty * 16 + 0];
            ulonglong2 a23 = *(const ulonglong2*)&As2[k][ty * 16 + 4];
            ulonglong2 a45 = *(const ulonglong2*)&As2[k][ty * 16 + 8];
            ulonglong2 a67 = *(const ulonglong2*)&As2[k][ty * 16 + 12];
            ulonglong2 b01 = *(const ulonglong2*)&Bs[k][tx * 8];
            ulonglong2 b23 = *(const ulonglong2*)&Bs[k][tx * 8 + 4];
            ull A[8] = {a01.x, a01.y, a23.x, a23.y, a45.x, a45.y, a67.x, a67.y};
            ull B[4] = {b01.x, b01.y, b23.x, b23.y};
#pragma unroll
            for (int i = 0; i < 8; i++) {
                ffma2(acc[i][0], A[i], B[0]);
                ffma2(acc[i][1], A[i], B[1]);
                ffma2(acc[i][2], A[i], B[2]);
                ffma2(acc[i][3], A[i], B[3]);
            }
        }
        __syncthreads();
    }
#pragma unroll
    for (int i = 0; i < 8; i++) {
        int grow = rowBase + ty * 8 + i;
        if (grow < Nn) {
            float* dst = &g_mm[(size_t)grow * Dd + bn * 128 + tx * 8];
            *(ulonglong2*)dst       = make_ulonglong2(acc[i][0], acc[i][1]);
            *(ulonglong2*)(dst + 4) = make_ulonglong2(acc[i][2], acc[i][3]);
        }
    }
}

// ---------------- aggregation + fused BN stats (layers 1-3) --------------
// grid = Nn/4 blocks exactly (Nn % 4 == 0), 256 threads: 4 nodes x 64 lanes.
__global__ void k_aggregate() {
    __shared__ float sS[4][256];
    __shared__ float sQ[4][256];

    int nib  = threadIdx.x >> 6;            // node in block, 0..3
    int lane = threadIdx.x & 63;            // float4 lane
    int node = blockIdx.x * 4 + nib;

    const float4* mmv = (const float4*)g_mm;
    float di = g_dinv[node];
    float4 acc = mmv[(size_t)node * 64 + lane];
    float sc = di * di;
    acc.x *= sc; acc.y *= sc; acc.z *= sc; acc.w *= sc;

    int s0 = g_off[node], s1 = g_off[node + 1];
    for (int k = s0; k < s1; k++) {
        int s = g_ssrc[k];
        float c = g_coef[k];
        float4 v = mmv[(size_t)s * 64 + lane];
        acc.x += c * v.x; acc.y += c * v.y; acc.z += c * v.z; acc.w += c * v.w;
    }
    ((float4*)g_agg)[(size_t)node * 64 + lane] = acc;

    // per-block BN stats partials
    int c0 = lane * 4;
    sS[nib][c0 + 0] = acc.x; sS[nib][c0 + 1] = acc.y;
    sS[nib][c0 + 2] = acc.z; sS[nib][c0 + 3] = acc.w;
    sQ[nib][c0 + 0] = acc.x * acc.x; sQ[nib][c0 + 1] = acc.y * acc.y;
    sQ[nib][c0 + 2] = acc.z * acc.z; sQ[nib][c0 + 3] = acc.w * acc.w;
    __syncthreads();
    int t = threadIdx.x;
    float s = sS[0][t] + sS[1][t] + sS[2][t] + sS[3][t];
    float q = sQ[0][t] + sQ[1][t] + sQ[2][t] + sQ[3][t];
    atomicAdd(&g_sum[t], s);
    atomicAdd(&g_sumsq[t], q);
}

// ---------------- layer-0 aggregation on F=64: g_ax = S @ x ----------------
__global__ void k_aggregate_x(const float* __restrict__ x) {
    int node = blockIdx.x * 16 + (threadIdx.x >> 4);
    int lane = threadIdx.x & 15;
    if (node >= Nn) return;

    const float4* xv = (const float4*)x;
    float di = g_dinv[node];
    float4 acc = xv[(size_t)node * 16 + lane];
    float sc = di * di;
    acc.x *= sc; acc.y *= sc; acc.z *= sc; acc.w *= sc;

    int s0 = g_off[node], s1 = g_off[node + 1];
    for (int k = s0; k < s1; k++) {
        int s = g_ssrc[k];
        float c = g_coef[k];
        float4 v = xv[(size_t)s * 16 + lane];
        acc.x += c * v.x; acc.y += c * v.y; acc.z += c * v.z; acc.w += c * v.w;
    }
    ((float4*)g_ax)[(size_t)node * 16 + lane] = acc;
}

// ---------------- batch-norm ----------------
__global__ void k_zero_stats() {
    int t = threadIdx.x;
    if (t < Dd) { g_sum[t] = 0.f; g_sumsq[t] = 0.f; }
}

// layer-0 stats over g_mm
__global__ void k_stats_mm() {
    int f = threadIdx.x;
    int r0 = blockIdx.x * 64;
    int r1 = r0 + 64; if (r1 > Nn) r1 = Nn;
    float sm = 0.f, sq = 0.f;
    for (int r = r0; r < r1; r++) {
        float v = g_mm[(size_t)r * Dd + f];
        sm += v;
        sq += v * v;
    }
    atomicAdd(&g_sum[f], sm);
    atomicAdd(&g_sumsq[f], sq);
}

__global__ void k_norm_tanh(const float* __restrict__ gamma, const float* __restrict__ beta,
                            int fromMM) {
    const float4* src = fromMM ? (const float4*)g_mm : (const float4*)g_agg;
    int idx = blockIdx.x * blockDim.x + threadIdx.x;
    if (idx >= Nn * 64) return;
    int c4 = idx & 63;
    int f = c4 * 4;
    float4 v = src[idx];
    const float invN = 1.0f / (float)Nn;
    float r[4] = {v.x, v.y, v.z, v.w};
#pragma unroll
    for (int j = 0; j < 4; j++) {
        float mu = g_sum[f + j] * invN;
        float var = g_sumsq[f + j] * invN - mu * mu;
        float sc = gamma[f + j] * rsqrtf(var + BN_EPS);
        r[j] = tanh_fast((r[j] - mu) * sc + beta[f + j]);
    }
    ((float4*)g_h)[idx] = make_float4(r[0], r[1], r[2], r[3]);
}

// ---------------- pooling + head ----------------
__device__ __forceinline__ int lower_bound_dev(const int* a, int n, int key) {
    int lo = 0, hi = n;
    while (lo < hi) {
        int mid = (lo + hi) >> 1;
        if (a[mid] < key) lo = mid + 1; else hi = mid;
    }
    return lo;
}

__global__ void k_pool(const int* __restrict__ batch, float* __restrict__ hidden) {
    __shared__ int s_lo, s_hi;
    int g = blockIdx.x;
    int f = threadIdx.x;
    if (f == 0) s_lo = lower_bound_dev(batch, Nn, g);
    if (f == 1) s_hi = lower_bound_dev(batch, Nn, g + 1);
    __syncthreads();
    int lo = s_lo, hi = s_hi;
    float mx = -3.4e38f, sm = 0.f;
    for (int n = lo; n < hi; n++) {
        float v = g_h[(size_t)n * Dd + f];
        mx = fmaxf(mx, v);
        sm += v;
    }
    float cnt = (float)(hi - lo);
    hidden[(size_t)g * 512 + f] = mx;
    hidden[(size_t)g * 512 + 256 + f] = sm / cnt;
}

__global__ void k_head(const float* __restrict__ hidden, const float* __restrict__ Wout,
                       const float* __restrict__ bout, float* __restrict__ out) {
    __shared__ float sm[512];
    int g = blockIdx.x;
    int t = threadIdx.x;
    sm[t] = hidden[(size_t)g * 512 + t] * Wout[t];
    __syncthreads();
    for (int s = 256; s > 0; s >>= 1) {
        if (t < s) sm[t] += sm[t + s];
        __syncthreads();
    }
    if (t == 0) out[g] = sm[0] + bout[0];
}

// ---------------- launch ----------------
extern "C" void kernel_launch(void* const* d_in, const int* in_sizes, int n_in,
                              void* d_out, int out_size) {
    const float* x     = (const float*)d_in[0];
    const int*   ei    = (const int*)d_in[1];
    const int*   batch = (const int*)d_in[2];
    const float* W[4]   = {(const float*)d_in[4], (const float*)d_in[6],
                           (const float*)d_in[8], (const float*)d_in[10]};
    const float* gam[4] = {(const float*)d_in[12], (const float*)d_in[14],
                           (const float*)d_in[16], (const float*)d_in[18]};
    const float* bet[4] = {(const float*)d_in[13], (const float*)d_in[15],
                           (const float*)d_in[17], (const float*)d_in[19]};
    const float* Wout = (const float*)d_in[20];
    const float* bout = (const float*)d_in[21];

    float* out    = (float*)d_out;        // [Bg]
    float* hidden = out + Bg;             // [Bg, 512]

    // graph preprocessing (CSR build)
    k_zero_graph<<<(Nn + 255) / 256, 256>>>();
    k_degree<<<(Ee + 255) / 256, 256>>>(ei);
    k_scan<<<1, 1024>>>();
    k_scatter<<<(Ee + 255) / 256, 256>>>(ei);

    dim3 gemmGrid(Dd / 128, (Nn + 127) / 128);

    // Layer 0: (S @ x) @ W0  (biases dropped: BN(z+b) == BN(z))
    k_aggregate_x<<<(Nn + 15) / 16, 256>>>(x);
    k_gemm<<<gemmGrid, 256>>>(W[0], Fin, 1);
    k_zero_stats<<<1, 256>>>();
    k_stats_mm<<<(Nn + 63) / 64, 256>>>();
    k_norm_tanh<<<(Nn * 64 + 255) / 256, 256>>>(gam[0], bet[0], 1);

    // Layers 1-3: S @ (h @ W), stats fused into aggregation
    for (int l = 1; l < 4; l++) {
        k_gemm<<<gemmGrid, 256>>>(W[l], Dd, 0);
        k_zero_stats<<<1, 256>>>();
        k_aggregate<<<Nn / 4, 256>>>();
        k_norm_tanh<<<(Nn * 64 + 255) / 256, 256>>>(gam[l], bet[l], 0);
    }

    k_pool<<<Bg, 256>>>(batch, hidden);
    k_head<<<Bg, 512>>>(hidden, Wout, bout, out);
}

// round 17
// speedup vs baseline: 1.0004x; 1.0004x over previous
#include <cuda_runtime.h>
#include <cuda_bf16.h>

#define Nn 50000
#define Ee 800000
#define Dd 256
#define Fin 64
#define Bg 1000
#define BN_EPS 1e-5f

typedef unsigned long long ull;

// ---------------- scratch (device globals; no allocation) ----------------
__device__ float g_mm[Nn * Dd];      // matmul output
__device__ float g_agg[Nn * Dd];     // aggregated
__device__ float g_h[Nn * Dd];       // layer activation
__device__ float g_ax[Nn * Fin];     // S @ x  (layer-0 pre-aggregated input)
__device__ int   g_cnt[Nn];
__device__ float g_dinv[Nn];
__device__ int   g_off[Nn + 1];
__device__ int   g_cur[Nn];
__device__ int   g_ssrc[Ee];
__device__ float g_coef[Ee];
__device__ float g_sum[Dd];
__device__ float g_sumsq[Dd];

// ---------------- f32x2 helper ----------------
__device__ __forceinline__ void ffma2(ull& d, ull a, ull b) {
    asm("fma.rn.f32x2 %0, %1, %2, %0;" : "+l"(d) : "l"(a), "l"(b));
}
__device__ __forceinline__ float tanh_fast(float x) {
    float y;
    asm("tanh.approx.f32 %0, %1;" : "=f"(y) : "f"(x));
    return y;
}

// ---------------- graph preprocessing ----------------
__global__ void k_zero_graph() {
    int i = blockIdx.x * blockDim.x + threadIdx.x;
    if (i < Nn) { g_cnt[i] = 0; g_cur[i] = 0; }
}

__global__ void k_degree(const int* __restrict__ ei) {
    int e = blockIdx.x * blockDim.x + threadIdx.x;
    if (e < Ee) atomicAdd(&g_cnt[ei[Ee + e]], 1);
}

__global__ void k_scan() {
    const int T = 1024;
    const int chunk = (Nn + T - 1) / T;
    __shared__ int s[T];
    int t = threadIdx.x;
    int beg = t * chunk;
    int end = beg + chunk; if (end > Nn) end = Nn;
    int loc = 0;
    for (int i = beg; i < end; i++) loc += g_cnt[i];
    s[t] = loc;
    __syncthreads();
    for (int d = 1; d < T; d <<= 1) {
        int v = (t >= d) ? s[t - d] : 0;
        __syncthreads();
        s[t] += v;
        __syncthreads();
    }
    int prefix = (t == 0) ? 0 : s[t - 1];
    for (int i = beg; i < end; i++) {
        g_off[i] = prefix;
        prefix += g_cnt[i];
    }
    if (t == T - 1) g_off[Nn] = prefix;
    for (int i = t; i < Nn; i += T) g_dinv[i] = rsqrtf(1.0f + (float)g_cnt[i]);
}

__global__ void k_scatter(const int* __restrict__ ei) {
    int e = blockIdx.x * blockDim.x + threadIdx.x;
    if (e >= Ee) return;
    int s = ei[e];
    int d = ei[Ee + e];
    int pos = g_off[d] + atomicAdd(&g_cur[d], 1);
    g_ssrc[pos] = s;
    g_coef[pos] = g_dinv[s] * g_dinv[d];
}

// ---------------- SGEMM (pure FFMA2): C[N,Dd] = A[N,K] @ W[K,Dd] ----------
// BM=128, BN=128, BK=16, 256 threads, 8x8 micro-tile = 8x4 f32x2 pairs.
// A tile stored DUPLICATED in smem: As2[k][2m]=As2[k][2m+1]=A[m], so one
// LDS.128 delivers two packed (a,a) u64 operands — no MOV packing at all.
// sel: 0 -> A = g_h (K=256), 1 -> A = g_ax (K=64)
__global__ __launch_bounds__(256, 2)
void k_gemm(const float* __restrict__ W, int K, int sel) {
    const int BK = 16;
    __shared__ __align__(16) float As2[BK][256];   // 16 KB (duplicated)
    __shared__ __align__(16) float Bs[BK][128];    // 8 KB

    int bn = blockIdx.x;
    int bm = blockIdx.y;
    int tid = threadIdx.x;
    int tx = tid & 15, ty = tid >> 4;
    int rowBase = bm * 128;

    const float* Abase = sel ? g_ax : g_h;

    ull acc[8][4];
#pragma unroll
    for (int i = 0; i < 8; i++)
#pragma unroll
        for (int j = 0; j < 4; j++) acc[i][j] = 0ull;

    for (int k0 = 0; k0 < K; k0 += BK) {
        // A tile: 128 rows x 16 k, duplicated along m
#pragma unroll
        for (int l = 0; l < 2; l++) {
            int idx = tid * 2 + l;        // 0..511
            int m = idx >> 2;             // 0..127
            int k4 = idx & 3;             // 0..3
            int grow = rowBase + m;
            float4 v = make_float4(0.f, 0.f, 0.f, 0.f);
            if (grow < Nn)
                v = *(const float4*)&Abase[(size_t)grow * K + k0 + k4 * 4];
            int mm = 2 * m;
            As2[k4 * 4 + 0][mm] = v.x; As2[k4 * 4 + 0][mm + 1] = v.x;
            As2[k4 * 4 + 1][mm] = v.y; As2[k4 * 4 + 1][mm + 1] = v.y;
            As2[k4 * 4 + 2][mm] = v.z; As2[k4 * 4 + 2][mm + 1] = v.z;
            As2[k4 * 4 + 3][mm] = v.w; As2[k4 * 4 + 3][mm + 1] = v.w;
        }
        // B tile: 16 x 128
#pragma unroll
        for (int l = 0; l < 2; l++) {
            int idx = tid * 2 + l;
            int k = idx >> 5;
            int n4 = idx & 31;
            float4 v = *(const float4*)&W[(size_t)(k0 + k) * Dd + bn * 128 + n4 * 4];
            *(float4*)&Bs[k][n4 * 4] = v;
        }
        __syncthreads();
#pragma unroll
        for (int k = 0; k < BK; k++) {
            ulonglong2 a01 = *(const ulonglong2*)&As2[k][ty * 16 + 0];
            ulonglong2 a23 = *(const ulonglong2*)&As2[k][ty * 16 + 4];
            ulonglong2 a45 = *(const ulonglong2*)&As2[k][ty * 16 + 8];
            ulonglong2 a67 = *(const ulonglong2*)&As2[k][ty * 16 + 12];
            ulonglong2 b01 = *(const ulonglong2*)&Bs[k][tx * 8];
            ulonglong2 b23 = *(const ulonglong2*)&Bs[k][tx * 8 + 4];
            ull A[8] = {a01.x, a01.y, a23.x, a23.y, a45.x, a45.y, a67.x, a67.y};
            ull B[4] = {b01.x, b01.y, b23.x, b23.y};
#pragma unroll
            for (int i = 0; i < 8; i++) {
                ffma2(acc[i][0], A[i], B[0]);
                ffma2(acc[i][1], A[i], B[1]);
                ffma2(acc[i][2], A[i], B[2]);
                ffma2(acc[i][3], A[i], B[3]);
            }
        }
        __syncthreads();
    }
#pragma unroll
    for (int i = 0; i < 8; i++) {
        int grow = rowBase + ty * 8 + i;
        if (grow < Nn) {
            float* dst = &g_mm[(size_t)grow * Dd + bn * 128 + tx * 8];
            *(ulonglong2*)dst       = make_ulonglong2(acc[i][0], acc[i][1]);
            *(ulonglong2*)(dst + 4) = make_ulonglong2(acc[i][2], acc[i][3]);
        }
    }
}

// ---------------- aggregation + fused BN stats (layers 1-3) --------------
// grid = Nn/4 blocks exactly (Nn % 4 == 0), 256 threads: 4 nodes x 64 lanes.
__global__ void k_aggregate() {
    __shared__ float sS[4][256];
    __shared__ float sQ[4][256];

    int nib  = threadIdx.x >> 6;            // node in block, 0..3
    int lane = threadIdx.x & 63;            // float4 lane
    int node = blockIdx.x * 4 + nib;

    const float4* mmv = (const float4*)g_mm;
    float di = g_dinv[node];
    float4 acc = mmv[(size_t)node * 64 + lane];
    float sc = di * di;
    acc.x *= sc; acc.y *= sc; acc.z *= sc; acc.w *= sc;

    int s0 = g_off[node], s1 = g_off[node + 1];
    for (int k = s0; k < s1; k++) {
        int s = g_ssrc[k];
        float c = g_coef[k];
        float4 v = mmv[(size_t)s * 64 + lane];
        acc.x += c * v.x; acc.y += c * v.y; acc.z += c * v.z; acc.w += c * v.w;
    }
    ((float4*)g_agg)[(size_t)node * 64 + lane] = acc;

    // per-block BN stats partials
    int c0 = lane * 4;
    sS[nib][c0 + 0] = acc.x; sS[nib][c0 + 1] = acc.y;
    sS[nib][c0 + 2] = acc.z; sS[nib][c0 + 3] = acc.w;
    sQ[nib][c0 + 0] = acc.x * acc.x; sQ[nib][c0 + 1] = acc.y * acc.y;
    sQ[nib][c0 + 2] = acc.z * acc.z; sQ[nib][c0 + 3] = acc.w * acc.w;
    __syncthreads();
    int t = threadIdx.x;
    float s = sS[0][t] + sS[1][t] + sS[2][t] + sS[3][t];
    float q = sQ[0][t] + sQ[1][t] + sQ[2][t] + sQ[3][t];
    atomicAdd(&g_sum[t], s);
    atomicAdd(&g_sumsq[t], q);
}

// ---------------- layer-0 aggregation on F=64: g_ax = S @ x ----------------
__global__ void k_aggregate_x(const float* __restrict__ x) {
    int node = blockIdx.x * 16 + (threadIdx.x >> 4);
    int lane = threadIdx.x & 15;
    if (node >= Nn) return;

    const float4* xv = (const float4*)x;
    float di = g_dinv[node];
    float4 acc = xv[(size_t)node * 16 + lane];
    float sc = di * di;
    acc.x *= sc; acc.y *= sc; acc.z *= sc; acc.w *= sc;

    int s0 = g_off[node], s1 = g_off[node + 1];
    for (int k = s0; k < s1; k++) {
        int s = g_ssrc[k];
        float c = g_coef[k];
        float4 v = xv[(size_t)s * 16 + lane];
        acc.x += c * v.x; acc.y += c * v.y; acc.z += c * v.z; acc.w += c * v.w;
    }
    ((float4*)g_ax)[(size_t)node * 16 + lane] = acc;
}

// ---------------- batch-norm ----------------
__global__ void k_zero_stats() {
    int t = threadIdx.x;
    if (t < Dd) { g_sum[t] = 0.f; g_sumsq[t] = 0.f; }
}

// layer-0 stats over g_mm
__global__ void k_stats_mm() {
    int f = threadIdx.x;
    int r0 = blockIdx.x * 64;
    int r1 = r0 + 64; if (r1 > Nn) r1 = Nn;
    float sm = 0.f, sq = 0.f;
    for (int r = r0; r < r1; r++) {
        float v = g_mm[(size_t)r * Dd + f];
        sm += v;
        sq += v * v;
    }
    atomicAdd(&g_sum[f], sm);
    atomicAdd(&g_sumsq[f], sq);
}

__global__ void k_norm_tanh(const float* __restrict__ gamma, const float* __restrict__ beta,
                            int fromMM) {
    const float4* src = fromMM ? (const float4*)g_mm : (const float4*)g_agg;
    int idx = blockIdx.x * blockDim.x + threadIdx.x;
    if (idx >= Nn * 64) return;
    int c4 = idx & 63;
    int f = c4 * 4;
    float4 v = src[idx];
    const float invN = 1.0f / (float)Nn;
    float r[4] = {v.x, v.y, v.z, v.w};
#pragma unroll
    for (int j = 0; j < 4; j++) {
        float mu = g_sum[f + j] * invN;
        float var = g_sumsq[f + j] * invN - mu * mu;
        float sc = gamma[f + j] * rsqrtf(var + BN_EPS);
        r[j] = tanh_fast((r[j] - mu) * sc + beta[f + j]);
    }
    ((float4*)g_h)[idx] = make_float4(r[0], r[1], r[2], r[3]);
}

// ---------------- pooling + head ----------------
__device__ __forceinline__ int lower_bound_dev(const int* a, int n, int key) {
    int lo = 0, hi = n;
    while (lo < hi) {
        int mid = (lo + hi) >> 1;
        if (a[mid] < key) lo = mid + 1; else hi = mid;
    }
    return lo;
}

__global__ void k_pool(const int* __restrict__ batch, float* __restrict__ hidden) {
    __shared__ int s_lo, s_hi;
    int g = blockIdx.x;
    int f = threadIdx.x;
    if (f == 0) s_lo = lower_bound_dev(batch, Nn, g);
    if (f == 1) s_hi = lower_bound_dev(batch, Nn, g + 1);
    __syncthreads();
    int lo = s_lo, hi = s_hi;
    float mx = -3.4e38f, sm = 0.f;
    for (int n = lo; n < hi; n++) {
        float v = g_h[(size_t)n * Dd + f];
        mx = fmaxf(mx, v);
        sm += v;
    }
    float cnt = (float)(hi - lo);
    hidden[(size_t)g * 512 + f] = mx;
    hidden[(size_t)g * 512 + 256 + f] = sm / cnt;
}

__global__ void k_head(const float* __restrict__ hidden, const float* __restrict__ Wout,
                       const float* __restrict__ bout, float* __restrict__ out) {
    __shared__ float sm[512];
    int g = blockIdx.x;
    int t = threadIdx.x;
    sm[t] = hidden[(size_t)g * 512 + t] * Wout[t];
    __syncthreads();
    for (int s = 256; s > 0; s >>= 1) {
        if (t < s) sm[t] += sm[t + s];
        __syncthreads();
    }
    if (t == 0) out[g] = sm[0] + bout[0];
}

// ---------------- launch ----------------
extern "C" void kernel_launch(void* const* d_in, const int* in_sizes, int n_in,
                              void* d_out, int out_size) {
    const float* x     = (const float*)d_in[0];
    const int*   ei    = (const int*)d_in[1];
    const int*   batch = (const int*)d_in[2];
    const float* W[4]   = {(const float*)d_in[4], (const float*)d_in[6],
                           (const float*)d_in[8], (const float*)d_in[10]};
    const float* gam[4] = {(const float*)d_in[12], (const float*)d_in[14],
                           (const float*)d_in[16], (const float*)d_in[18]};
    const float* bet[4] = {(const float*)d_in[13], (const float*)d_in[15],
                           (const float*)d_in[17], (const float*)d_in[19]};
    const float* Wout = (const float*)d_in[20];
    const float* bout = (const float*)d_in[21];

    float* out    = (float*)d_out;        // [Bg]
    float* hidden = out + Bg;             // [Bg, 512]

    // graph preprocessing (CSR build)
    k_zero_graph<<<(Nn + 255) / 256, 256>>>();
    k_degree<<<(Ee + 255) / 256, 256>>>(ei);
    k_scan<<<1, 1024>>>();
    k_scatter<<<(Ee + 255) / 256, 256>>>(ei);

    dim3 gemmGrid(Dd / 128, (Nn + 127) / 128);

    // Layer 0: (S @ x) @ W0  (biases dropped: BN(z+b) == BN(z))
    k_aggregate_x<<<(Nn + 15) / 16, 256>>>(x);
    k_gemm<<<gemmGrid, 256>>>(W[0], Fin, 1);
    k_zero_stats<<<1, 256>>>();
    k_stats_mm<<<(Nn + 63) / 64, 256>>>();
    k_norm_tanh<<<(Nn * 64 + 255) / 256, 256>>>(gam[0], bet[0], 1);

    // Layers 1-3: S @ (h @ W), stats fused into aggregation
    for (int l = 1; l < 4; l++) {
        k_gemm<<<gemmGrid, 256>>>(W[l], Dd, 0);
        k_zero_stats<<<1, 256>>>();
        k_aggregate<<<Nn / 4, 256>>>();
        k_norm_tanh<<<(Nn * 64 + 255) / 256, 256>>>(gam[l], bet[l], 0);
    }

    k_pool<<<Bg, 256>>>(batch, hidden);
    k_head<<<Bg, 512>>>(hidden, Wout, bout, out);
}